// round 7
// baseline (speedup 1.0000x reference)
#include <cuda_runtime.h>
#include <cstdint>

#define DINLINE __device__ __forceinline__

// ---------------- problem sizes ----------------
#define M_DIM 512
#define N_DIM 4096
#define K_DIM 4096

// ---------------- GEMM tiling (R3 config: best measured, 66.4us) ----------------
#define BM 64
#define BN 128
#define BK 64                        // fp8 elements per K-chunk
#define ROWB 80                      // padded smem row stride -> conflict-free ldmatrix
#define STAGES 4
#define KIT (K_DIM / BK)             // 64
#define TILE_A_BYTES (BM * ROWB)     // 5120
#define TILE_B_BYTES (BN * ROWB)     // 10240
#define STAGE_BYTES (TILE_A_BYTES + TILE_B_BYTES)   // 15360
#define SMEM_TOTAL (STAGES * STAGE_BYTES)           // 61440 -> 2 CTAs/SM

// ---------------- fused amax+quantize kernel ----------------
#define FQ_BLOCKS 592                // 148 SMs * 4 CTAs, guaranteed co-resident
#define FQ_THREADS 256
#define FQ_NTHREADS (FQ_BLOCKS * FQ_THREADS)
#define N4_X ((M_DIM * K_DIM) / 4)   // 524288 float4
#define N4_W ((N_DIM * K_DIM) / 4)   // 4194304 float4
#define N16_X ((M_DIM * K_DIM) / 16) // 131072 uint4 outputs
#define N16_W ((N_DIM * K_DIM) / 16)

// ---------------- scratch (static device globals; no allocs allowed) ----------------
// codes: e4m3 encodings of 2*e2m1 codebook value, i.e. {0,1,2,3,4,6,8,12} signed
__device__ __align__(256) uint8_t g_xq[M_DIM * K_DIM];   // 2 MB
__device__ __align__(256) uint8_t g_wq[N_DIM * K_DIM];   // 16 MB
__device__ unsigned int g_amax_bits[2];
__device__ unsigned int g_bar;

// ---------------- PTX helpers ----------------
DINLINE uint32_t smem_u32(const void* p) {
    uint32_t a;
    asm("{ .reg .u64 t; cvta.to.shared.u64 t, %1; cvt.u32.u64 %0, t; }" : "=r"(a) : "l"(p));
    return a;
}

DINLINE void cp16(uint32_t dst, const void* src) {
    asm volatile("cp.async.cg.shared.global [%0], [%1], 16;" :: "r"(dst), "l"(src));
}
DINLINE void cp_commit() { asm volatile("cp.async.commit_group;" ::: "memory"); }

DINLINE void ldsm4(uint32_t* r, uint32_t addr) {
    asm volatile("ldmatrix.sync.aligned.m8n8.x4.shared.b16 {%0,%1,%2,%3}, [%4];"
                 : "=r"(r[0]), "=r"(r[1]), "=r"(r[2]), "=r"(r[3]) : "r"(addr));
}

// fp8 e4m3 MMA, f32 accumulate.
DINLINE void mma_f8(float* c, const uint32_t* a, const uint32_t* b) {
    asm volatile(
        "mma.sync.aligned.m16n8k32.row.col.f32.e4m3.e4m3.f32 "
        "{%0,%1,%2,%3}, {%4,%5,%6,%7}, {%8,%9}, {%0,%1,%2,%3};"
        : "+f"(c[0]), "+f"(c[1]), "+f"(c[2]), "+f"(c[3])
        : "r"(a[0]), "r"(a[1]), "r"(a[2]), "r"(a[3]), "r"(b[0]), "r"(b[1]));
}

// ---------------- phase 0: init (zero amax + barrier counter) ----------------
__global__ void init_kernel() {
    if (threadIdx.x == 0) { g_amax_bits[0] = 0u; g_amax_bits[1] = 0u; g_bar = 0u; }
}

// ---------------- quantize helper ----------------
// nearest codebook magnitude, ties -> lower. Midpoints on |t|*scale:
//   0.25, 0.75, 1.25, 1.75, 2.5, 3.5, 5.0 ; strictly-greater moves up.
// e4m3 encodings of {0,1,2,3,4,6,8,12}: 00,38,40,44,48,4C,50,54
DINLINE uint32_t qbyte(float v, float s) {
    float a = __fmul_rn(fabsf(v), s);
    int idx = a > 5.0f  ? 7
            : a > 3.5f  ? 6
            : a > 2.5f  ? 5
            : a > 1.75f ? 4
            : a > 1.25f ? 3
            : a > 0.75f ? 2
            : a > 0.25f ? 1 : 0;
    uint32_t b = (uint32_t)((0x54504C4844403800ull >> (idx * 8)) & 0xff);
    return b | (v < 0.0f ? 0x80u : 0u);
}

DINLINE float amax_f4(float4 v, float m) {
    return fmaxf(m, fmaxf(fmaxf(fabsf(v.x), fabsf(v.y)), fmaxf(fabsf(v.z), fabsf(v.w))));
}

// ---------------- phase 1+2 fused: amax then quantize, grid-wide barrier between ----------------
__global__ void __launch_bounds__(FQ_THREADS) fused_quant_kernel(const float4* __restrict__ x,
                                                                 const float4* __restrict__ w) {
    const int tid = threadIdx.x;
    const unsigned gtid = blockIdx.x * FQ_THREADS + tid;

    // ---- phase A: amax over x and w ----
    float mx = 0.0f, mw = 0.0f;
    {
        unsigned i = gtid;
        // N4_X / FQ_NTHREADS = 3.46 -> up to 4 iterations
        for (; i + 3u * FQ_NTHREADS < N4_X; i += 4u * FQ_NTHREADS) {
            float4 v0 = x[i];
            float4 v1 = x[i + FQ_NTHREADS];
            float4 v2 = x[i + 2u * FQ_NTHREADS];
            float4 v3 = x[i + 3u * FQ_NTHREADS];
            mx = amax_f4(v0, mx); mx = amax_f4(v1, mx);
            mx = amax_f4(v2, mx); mx = amax_f4(v3, mx);
        }
        for (; i < N4_X; i += FQ_NTHREADS) mx = amax_f4(x[i], mx);
    }
    {
        unsigned i = gtid;
        for (; i + 3u * FQ_NTHREADS < N4_W; i += 4u * FQ_NTHREADS) {
            float4 v0 = w[i];
            float4 v1 = w[i + FQ_NTHREADS];
            float4 v2 = w[i + 2u * FQ_NTHREADS];
            float4 v3 = w[i + 3u * FQ_NTHREADS];
            mw = amax_f4(v0, mw); mw = amax_f4(v1, mw);
            mw = amax_f4(v2, mw); mw = amax_f4(v3, mw);
        }
        for (; i < N4_W; i += FQ_NTHREADS) mw = amax_f4(w[i], mw);
    }
    // block reduce
#pragma unroll
    for (int o = 16; o; o >>= 1) {
        mx = fmaxf(mx, __shfl_xor_sync(0xffffffffu, mx, o));
        mw = fmaxf(mw, __shfl_xor_sync(0xffffffffu, mw, o));
    }
    __shared__ float smx[8], smw[8];
    if ((tid & 31) == 0) { smx[tid >> 5] = mx; smw[tid >> 5] = mw; }
    __syncthreads();
    if (tid == 0) {
        float bx = smx[0], bw = smw[0];
#pragma unroll
        for (int i = 1; i < 8; i++) { bx = fmaxf(bx, smx[i]); bw = fmaxf(bw, smw[i]); }
        // values >= 0 -> int bit compare == float compare
        atomicMax(reinterpret_cast<int*>(&g_amax_bits[0]), __float_as_int(bx));
        atomicMax(reinterpret_cast<int*>(&g_amax_bits[1]), __float_as_int(bw));
    }

    // ---- grid-wide barrier (all FQ_BLOCKS co-resident by construction) ----
    __syncthreads();
    if (tid == 0) {
        __threadfence();
        atomicAdd(&g_bar, 1u);
        while (atomicAdd(&g_bar, 0u) < FQ_BLOCKS) { __nanosleep(64); }
    }
    __syncthreads();

    // ---- phase B: quantize (reads are L2-hot from phase A) ----
    float ax = fmaxf(__uint_as_float(__ldcg(&g_amax_bits[0])), 1e-12f);
    float aw = fmaxf(__uint_as_float(__ldcg(&g_amax_bits[1])), 1e-12f);
    float sx = __fdiv_rn(6.0f, ax);
    float sw = __fdiv_rn(6.0f, aw);

    for (unsigned c = gtid; c < N16_X; c += FQ_NTHREADS) {
        float4 v[4];
#pragma unroll
        for (int j = 0; j < 4; j++) v[j] = x[c * 4 + j];
        uint32_t wd[4];
#pragma unroll
        for (int j = 0; j < 4; j++)
            wd[j] = qbyte(v[j].x, sx) | (qbyte(v[j].y, sx) << 8)
                  | (qbyte(v[j].z, sx) << 16) | (qbyte(v[j].w, sx) << 24);
        reinterpret_cast<uint4*>(g_xq)[c] = make_uint4(wd[0], wd[1], wd[2], wd[3]);
    }
    for (unsigned c = gtid; c < N16_W; c += FQ_NTHREADS) {
        float4 v[4];
#pragma unroll
        for (int j = 0; j < 4; j++) v[j] = w[c * 4 + j];
        uint32_t wd[4];
#pragma unroll
        for (int j = 0; j < 4; j++)
            wd[j] = qbyte(v[j].x, sw) | (qbyte(v[j].y, sw) << 8)
                  | (qbyte(v[j].z, sw) << 16) | (qbyte(v[j].w, sw) << 24);
        reinterpret_cast<uint4*>(g_wq)[c] = make_uint4(wd[0], wd[1], wd[2], wd[3]);
    }
}

// ---------------- phase 3: fp8 QMMA GEMM (R3 config) ----------------
// C[64,128] per CTA; 8 warps (2x4), warp tile 32x32. BK=64 -> 2 k32 steps/stage.
// 256 CTAs, 2 CTAs/SM.

__global__ void __launch_bounds__(256, 2) gemm_kernel(float* __restrict__ out) {
    extern __shared__ char smem[];
    uint32_t sb = smem_u32(smem);
    const int tid = threadIdx.x;
    const int lane = tid & 31, wid = tid >> 5;
    const int wm = wid >> 2, wn = wid & 3;
    const int bm = blockIdx.x & 7, bn = blockIdx.x >> 3;
    const uint8_t* Ag = g_xq + (size_t)bm * BM * K_DIM;
    const uint8_t* Bg = g_wq + (size_t)bn * BN * K_DIM;

    // cp.async mapping: 768 x 16B chunks per stage (A 256 + B 512), 3 per thread
    uint32_t soff[3];
    const uint8_t* gp[3];
#pragma unroll
    for (int j = 0; j < 3; j++) {
        int idx = tid + j * 256;
        if (idx < 256) {                      // A: 64 rows x 4 chunks
            int row = idx >> 2, ch = idx & 3;
            soff[j] = (uint32_t)(row * ROWB + ch * 16);
            gp[j] = Ag + (size_t)row * K_DIM + ch * 16;
        } else {                              // B: 128 rows x 4 chunks
            int r2 = idx - 256;
            int row = r2 >> 2, ch = r2 & 3;
            soff[j] = (uint32_t)(TILE_A_BYTES + row * ROWB + ch * 16);
            gp[j] = Bg + (size_t)row * K_DIM + ch * 16;
        }
    }

    // per-lane ldmatrix offsets
    uint32_t offA[2][2], offB[2][2];
    {
        int rA = wm * 32 + (lane & 15);
        int kA = (lane & 16);
#pragma unroll
        for (int mt = 0; mt < 2; mt++)
#pragma unroll
            for (int ks = 0; ks < 2; ks++)
                offA[mt][ks] = (uint32_t)((rA + mt * 16) * ROWB + ks * 32 + kA);
        int mB = lane >> 3;
        int rB = wn * 32 + (mB >> 1) * 8 + (lane & 7);
        int kB = (mB & 1) * 16;
#pragma unroll
        for (int np = 0; np < 2; np++)
#pragma unroll
            for (int ks = 0; ks < 2; ks++)
                offB[np][ks] = (uint32_t)(TILE_A_BYTES + (rB + np * 16) * ROWB + ks * 32 + kB);
    }

    float acc[2][4][4];
#pragma unroll
    for (int mt = 0; mt < 2; mt++)
#pragma unroll
        for (int nt = 0; nt < 4; nt++)
#pragma unroll
            for (int i = 0; i < 4; i++) acc[mt][nt][i] = 0.0f;

    // prologue: fill STAGES-1 stages
#pragma unroll
    for (int s = 0; s < STAGES - 1; s++) {
#pragma unroll
        for (int j = 0; j < 3; j++) cp16(sb + s * STAGE_BYTES + soff[j], gp[j] + s * BK);
        cp_commit();
    }

    for (int k = 0; k < KIT; k++) {
        const int s = k & (STAGES - 1);
        if (k < KIT - 2)       asm volatile("cp.async.wait_group 2;" ::: "memory");
        else if (k == KIT - 2) asm volatile("cp.async.wait_group 1;" ::: "memory");
        else                   asm volatile("cp.async.wait_group 0;" ::: "memory");
        __syncthreads();

        // prefetch stage k+3 into the slot retired at iteration k-1
        int kp = k + STAGES - 1;
        if (kp < KIT) {
            uint32_t sp = sb + (uint32_t)(kp & (STAGES - 1)) * STAGE_BYTES;
#pragma unroll
            for (int j = 0; j < 3; j++) cp16(sp + soff[j], gp[j] + kp * BK);
            cp_commit();
        }

        uint32_t base = sb + (uint32_t)s * STAGE_BYTES;
#pragma unroll
        for (int ks = 0; ks < 2; ks++) {
            uint32_t a[2][4], b[2][4];
#pragma unroll
            for (int mt = 0; mt < 2; mt++) ldsm4(a[mt], base + offA[mt][ks]);
#pragma unroll
            for (int np = 0; np < 2; np++) ldsm4(b[np], base + offB[np][ks]);
#pragma unroll
            for (int mt = 0; mt < 2; mt++) {
#pragma unroll
                for (int nt = 0; nt < 4; nt++) {
                    const uint32_t* bf = &b[nt >> 1][(nt & 1) * 2];
                    mma_f8(acc[mt][nt], a[mt], bf);
                }
            }
        }
    }

    // epilogue: scale by inv_scale_x * inv_scale_w / 4 (codes are 2x codebook values)
    float ax = fmaxf(__uint_as_float(g_amax_bits[0]), 1e-12f);
    float aw = fmaxf(__uint_as_float(g_amax_bits[1]), 1e-12f);
    float invx = __fdiv_rn(1.0f, __fdiv_rn(6.0f, ax));
    float invw = __fdiv_rn(1.0f, __fdiv_rn(6.0f, aw));
    float scl = invx * invw * 0.25f;

    int row0 = bm * BM + wm * 32 + (lane >> 2);
    int col0 = bn * BN + wn * 32 + (lane & 3) * 2;
#pragma unroll
    for (int mt = 0; mt < 2; mt++) {
#pragma unroll
        for (int nt = 0; nt < 4; nt++) {
            float2 v0, v1;
            v0.x = acc[mt][nt][0] * scl;
            v0.y = acc[mt][nt][1] * scl;
            v1.x = acc[mt][nt][2] * scl;
            v1.y = acc[mt][nt][3] * scl;
            int r = row0 + mt * 16;
            int c = col0 + nt * 8;
            *reinterpret_cast<float2*>(out + (size_t)r * N_DIM + c) = v0;
            *reinterpret_cast<float2*>(out + (size_t)(r + 8) * N_DIM + c) = v1;
        }
    }
}

// ---------------- launch ----------------
extern "C" void kernel_launch(void* const* d_in, const int* in_sizes, int n_in,
                              void* d_out, int out_size) {
    const float* x = (const float*)d_in[0];       // [512, 4096]
    const float* w = (const float*)d_in[1];       // [4096, 4096]
    float* out = (float*)d_out;                   // [512, 4096] fp32

    cudaFuncSetAttribute(gemm_kernel, cudaFuncAttributeMaxDynamicSharedMemorySize, SMEM_TOTAL);

    init_kernel<<<1, 32>>>();
    fused_quant_kernel<<<FQ_BLOCKS, FQ_THREADS>>>((const float4*)x, (const float4*)w);
    gemm_kernel<<<(M_DIM / BM) * (N_DIM / BN), 256, SMEM_TOTAL>>>(out);
}

// round 8
// speedup vs baseline: 1.0707x; 1.0707x over previous
#include <cuda_runtime.h>
#include <cstdint>

#define DINLINE __device__ __forceinline__

// ---------------- problem sizes ----------------
#define M_DIM 512
#define N_DIM 4096
#define K_DIM 4096

// ---------------- GEMM tiling (best measured config) ----------------
#define BM 64
#define BN 128
#define BK 64                        // fp8 elements per K-chunk
#define ROWB 80                      // padded smem row stride -> conflict-free ldmatrix
#define STAGES 4
#define KIT (K_DIM / BK)             // 64
#define TILE_A_BYTES (BM * ROWB)     // 5120
#define TILE_B_BYTES (BN * ROWB)     // 10240
#define STAGE_BYTES (TILE_A_BYTES + TILE_B_BYTES)   // 15360
#define SMEM_TOTAL (STAGES * STAGE_BYTES)           // 61440 -> 2 CTAs/SM

// ---------------- amax/quantize grids (exact cover) ----------------
#define AMAX_X_BLOCKS 256
#define AMAX_W_BLOCKS 2048
#define QUANT_X_BLOCKS 512
#define QUANT_W_BLOCKS 4096

// ---------------- scratch (static device globals; no allocs allowed) ----------------
// codes: e4m3 encodings of 2*e2m1 codebook value, i.e. {0,1,2,3,4,6,8,12} signed
__device__ __align__(256) uint8_t g_xq[M_DIM * K_DIM];   // 2 MB
__device__ __align__(256) uint8_t g_wq[N_DIM * K_DIM];   // 16 MB
__device__ unsigned int g_amax_bits[2];                  // zero-init; gemm tail re-zeroes

// ---------------- PTX helpers ----------------
DINLINE uint32_t smem_u32(const void* p) {
    uint32_t a;
    asm("{ .reg .u64 t; cvta.to.shared.u64 t, %1; cvt.u32.u64 %0, t; }" : "=r"(a) : "l"(p));
    return a;
}

DINLINE void cp16(uint32_t dst, const void* src) {
    asm volatile("cp.async.cg.shared.global [%0], [%1], 16;" :: "r"(dst), "l"(src));
}
DINLINE void cp_commit() { asm volatile("cp.async.commit_group;" ::: "memory"); }

DINLINE void ldsm4(uint32_t* r, uint32_t addr) {
    asm volatile("ldmatrix.sync.aligned.m8n8.x4.shared.b16 {%0,%1,%2,%3}, [%4];"
                 : "=r"(r[0]), "=r"(r[1]), "=r"(r[2]), "=r"(r[3]) : "r"(addr));
}

// fp8 e4m3 MMA, f32 accumulate.
DINLINE void mma_f8(float* c, const uint32_t* a, const uint32_t* b) {
    asm volatile(
        "mma.sync.aligned.m16n8k32.row.col.f32.e4m3.e4m3.f32 "
        "{%0,%1,%2,%3}, {%4,%5,%6,%7}, {%8,%9}, {%0,%1,%2,%3};"
        : "+f"(c[0]), "+f"(c[1]), "+f"(c[2]), "+f"(c[3])
        : "r"(a[0]), "r"(a[1]), "r"(a[2]), "r"(a[3]), "r"(b[0]), "r"(b[1]));
}

// ---------------- phase 1: fused amax (exact fp32 max of |t|), MLP=8 ----------------
__global__ void __launch_bounds__(256) amax_kernel(const float4* __restrict__ x,
                                                   const float4* __restrict__ w) {
    const float4* in;
    int which;
    if (blockIdx.x < AMAX_X_BLOCKS) {
        in = x + (size_t)blockIdx.x * 2048;
        which = 0;
    } else {
        in = w + (size_t)(blockIdx.x - AMAX_X_BLOCKS) * 2048;
        which = 1;
    }
    float4 v[8];
#pragma unroll
    for (int j = 0; j < 8; j++) v[j] = in[threadIdx.x + j * 256];
    float m = 0.0f;
#pragma unroll
    for (int j = 0; j < 8; j++)
        m = fmaxf(m, fmaxf(fmaxf(fabsf(v[j].x), fabsf(v[j].y)),
                           fmaxf(fabsf(v[j].z), fabsf(v[j].w))));
#pragma unroll
    for (int o = 16; o; o >>= 1) m = fmaxf(m, __shfl_xor_sync(0xffffffffu, m, o));
    __shared__ float sm[8];
    if ((threadIdx.x & 31) == 0) sm[threadIdx.x >> 5] = m;
    __syncthreads();
    if (threadIdx.x == 0) {
        float b = sm[0];
#pragma unroll
        for (int i = 1; i < 8; i++) b = fmaxf(b, sm[i]);
        // values >= 0 -> int bit compare == float compare
        atomicMax(reinterpret_cast<int*>(&g_amax_bits[which]), __float_as_int(b));
    }
}

// ---------------- phase 2: fused quantize to e4m3 codes ----------------
// nearest codebook magnitude, ties -> lower. Midpoints on |t|*scale:
//   0.25, 0.75, 1.25, 1.75, 2.5, 3.5, 5.0 ; strictly-greater moves up.
// e4m3 encodings of {0,1,2,3,4,6,8,12}: 00,38,40,44,48,4C,50,54
DINLINE uint32_t qbyte(float v, float s) {
    float a = __fmul_rn(fabsf(v), s);
    int idx = a > 5.0f  ? 7
            : a > 3.5f  ? 6
            : a > 2.5f  ? 5
            : a > 1.75f ? 4
            : a > 1.25f ? 3
            : a > 0.75f ? 2
            : a > 0.25f ? 1 : 0;
    uint32_t b = (uint32_t)((0x54504C4844403800ull >> (idx * 8)) & 0xff);
    return b | (v < 0.0f ? 0x80u : 0u);
}

__global__ void __launch_bounds__(256) quantize_kernel(const float4* __restrict__ x,
                                                       const float4* __restrict__ w) {
    const float4* in;
    uint8_t* outp;
    size_t i;
    int which;
    if (blockIdx.x < QUANT_X_BLOCKS) {
        in = x; outp = g_xq; which = 0;
        i = (size_t)blockIdx.x * 256 + threadIdx.x;
    } else {
        in = w; outp = g_wq; which = 1;
        i = (size_t)(blockIdx.x - QUANT_X_BLOCKS) * 256 + threadIdx.x;
    }
    float amax = fmaxf(__uint_as_float(g_amax_bits[which]), 1e-12f);
    float s = __fdiv_rn(6.0f, amax);

    float4 v[4];
#pragma unroll
    for (int j = 0; j < 4; j++) v[j] = in[i * 4 + j];
    uint32_t wrd[4];
#pragma unroll
    for (int j = 0; j < 4; j++) {
        wrd[j] = qbyte(v[j].x, s)
               | (qbyte(v[j].y, s) << 8)
               | (qbyte(v[j].z, s) << 16)
               | (qbyte(v[j].w, s) << 24);
    }
    reinterpret_cast<uint4*>(outp)[i] = make_uint4(wrd[0], wrd[1], wrd[2], wrd[3]);
}

// ---------------- phase 3: fp8 QMMA GEMM ----------------
// C[64,128] per CTA; 8 warps (2x4), warp tile 32x32. BK=64 -> 2 k32 steps/stage.
// 256 CTAs (single wave, all co-resident), 2 CTAs/SM.
// Scales read in PROLOGUE; block 0 re-zeroes g_amax_bits at its tail so the
// next graph replay starts from a clean state without a separate init launch.

__global__ void __launch_bounds__(256, 2) gemm_kernel(float* __restrict__ out) {
    extern __shared__ char smem[];
    uint32_t sb = smem_u32(smem);
    const int tid = threadIdx.x;
    const int lane = tid & 31, wid = tid >> 5;
    const int wm = wid >> 2, wn = wid & 3;
    const int bm = blockIdx.x & 7, bn = blockIdx.x >> 3;
    const uint8_t* Ag = g_xq + (size_t)bm * BM * K_DIM;
    const uint8_t* Bg = g_wq + (size_t)bn * BN * K_DIM;

    // read scales NOW (every co-resident CTA reads before any CTA can finish)
    float ax = fmaxf(__uint_as_float(g_amax_bits[0]), 1e-12f);
    float aw = fmaxf(__uint_as_float(g_amax_bits[1]), 1e-12f);
    // scale = inv_scale_x * inv_scale_w / 4 (codes are 2x codebook values)
    float scl = __fdiv_rn(1.0f, __fdiv_rn(6.0f, ax)) *
                __fdiv_rn(1.0f, __fdiv_rn(6.0f, aw)) * 0.25f;

    // cp.async mapping: 768 x 16B chunks per stage (A 256 + B 512), 3 per thread
    uint32_t soff[3];
    const uint8_t* gp[3];
#pragma unroll
    for (int j = 0; j < 3; j++) {
        int idx = tid + j * 256;
        if (idx < 256) {                      // A: 64 rows x 4 chunks
            int row = idx >> 2, ch = idx & 3;
            soff[j] = (uint32_t)(row * ROWB + ch * 16);
            gp[j] = Ag + (size_t)row * K_DIM + ch * 16;
        } else {                              // B: 128 rows x 4 chunks
            int r2 = idx - 256;
            int row = r2 >> 2, ch = r2 & 3;
            soff[j] = (uint32_t)(TILE_A_BYTES + row * ROWB + ch * 16);
            gp[j] = Bg + (size_t)row * K_DIM + ch * 16;
        }
    }

    // per-lane ldmatrix offsets
    uint32_t offA[2][2], offB[2][2];
    {
        int rA = wm * 32 + (lane & 15);
        int kA = (lane & 16);
#pragma unroll
        for (int mt = 0; mt < 2; mt++)
#pragma unroll
            for (int ks = 0; ks < 2; ks++)
                offA[mt][ks] = (uint32_t)((rA + mt * 16) * ROWB + ks * 32 + kA);
        int mB = lane >> 3;
        int rB = wn * 32 + (mB >> 1) * 8 + (lane & 7);
        int kB = (mB & 1) * 16;
#pragma unroll
        for (int np = 0; np < 2; np++)
#pragma unroll
            for (int ks = 0; ks < 2; ks++)
                offB[np][ks] = (uint32_t)(TILE_A_BYTES + (rB + np * 16) * ROWB + ks * 32 + kB);
    }

    float acc[2][4][4];
#pragma unroll
    for (int mt = 0; mt < 2; mt++)
#pragma unroll
        for (int nt = 0; nt < 4; nt++)
#pragma unroll
            for (int i = 0; i < 4; i++) acc[mt][nt][i] = 0.0f;

    // prologue: fill STAGES-1 stages
#pragma unroll
    for (int s = 0; s < STAGES - 1; s++) {
#pragma unroll
        for (int j = 0; j < 3; j++) cp16(sb + s * STAGE_BYTES + soff[j], gp[j] + s * BK);
        cp_commit();
    }

    for (int k = 0; k < KIT; k++) {
        const int s = k & (STAGES - 1);
        if (k < KIT - 2)       asm volatile("cp.async.wait_group 2;" ::: "memory");
        else if (k == KIT - 2) asm volatile("cp.async.wait_group 1;" ::: "memory");
        else                   asm volatile("cp.async.wait_group 0;" ::: "memory");
        __syncthreads();

        // prefetch stage k+3 into the slot retired at iteration k-1
        int kp = k + STAGES - 1;
        if (kp < KIT) {
            uint32_t sp = sb + (uint32_t)(kp & (STAGES - 1)) * STAGE_BYTES;
#pragma unroll
            for (int j = 0; j < 3; j++) cp16(sp + soff[j], gp[j] + kp * BK);
            cp_commit();
        }

        uint32_t base = sb + (uint32_t)s * STAGE_BYTES;
#pragma unroll
        for (int ks = 0; ks < 2; ks++) {
            uint32_t a[2][4], b[2][4];
#pragma unroll
            for (int mt = 0; mt < 2; mt++) ldsm4(a[mt], base + offA[mt][ks]);
#pragma unroll
            for (int np = 0; np < 2; np++) ldsm4(b[np], base + offB[np][ks]);
#pragma unroll
            for (int mt = 0; mt < 2; mt++) {
#pragma unroll
                for (int nt = 0; nt < 4; nt++) {
                    const uint32_t* bf = &b[nt >> 1][(nt & 1) * 2];
                    mma_f8(acc[mt][nt], a[mt], bf);
                }
            }
        }
    }

    // epilogue
    int row0 = bm * BM + wm * 32 + (lane >> 2);
    int col0 = bn * BN + wn * 32 + (lane & 3) * 2;
#pragma unroll
    for (int mt = 0; mt < 2; mt++) {
#pragma unroll
        for (int nt = 0; nt < 4; nt++) {
            float2 v0, v1;
            v0.x = acc[mt][nt][0] * scl;
            v0.y = acc[mt][nt][1] * scl;
            v1.x = acc[mt][nt][2] * scl;
            v1.y = acc[mt][nt][3] * scl;
            int r = row0 + mt * 16;
            int c = col0 + nt * 8;
            *reinterpret_cast<float2*>(out + (size_t)r * N_DIM + c) = v0;
            *reinterpret_cast<float2*>(out + (size_t)(r + 8) * N_DIM + c) = v1;
        }
    }

    // reset amax accumulators for the next replay. All 256 CTAs are co-resident
    // (single wave) and read g_amax_bits in their prologue ~60us before this point.
    if (blockIdx.x == 0 && tid == 0) {
        g_amax_bits[0] = 0u;
        g_amax_bits[1] = 0u;
    }
}

// ---------------- launch ----------------
extern "C" void kernel_launch(void* const* d_in, const int* in_sizes, int n_in,
                              void* d_out, int out_size) {
    const float* x = (const float*)d_in[0];       // [512, 4096]
    const float* w = (const float*)d_in[1];       // [4096, 4096]
    float* out = (float*)d_out;                   // [512, 4096] fp32

    cudaFuncSetAttribute(gemm_kernel, cudaFuncAttributeMaxDynamicSharedMemorySize, SMEM_TOTAL);

    amax_kernel<<<AMAX_X_BLOCKS + AMAX_W_BLOCKS, 256>>>((const float4*)x, (const float4*)w);
    quantize_kernel<<<QUANT_X_BLOCKS + QUANT_W_BLOCKS, 256>>>((const float4*)x, (const float4*)w);
    gemm_kernel<<<(M_DIM / BM) * (N_DIM / BN), 256, SMEM_TOTAL>>>(out);
}

// round 9
// speedup vs baseline: 1.0944x; 1.0221x over previous
#include <cuda_runtime.h>
#include <cstdint>

#define DINLINE __device__ __forceinline__

// ---------------- problem sizes ----------------
#define M_DIM 512
#define N_DIM 4096
#define K_DIM 4096

// ---------------- GEMM tiling: 32x64 tiles, 1024 CTAs for SM load balance ----------------
#define BM 32
#define BN 64
#define BK 64                        // fp8 elements per K-chunk
#define ROWB 80                      // padded smem row stride -> conflict-free ldmatrix
#define STAGES 4
#define KIT (K_DIM / BK)             // 64
#define TILE_A_BYTES (BM * ROWB)     // 2560
#define TILE_B_BYTES (BN * ROWB)     // 5120
#define STAGE_BYTES (TILE_A_BYTES + TILE_B_BYTES)   // 7680
#define SMEM_TOTAL (STAGES * STAGE_BYTES)           // 30720 -> 7 CTAs/SM
#define GRID_GEMM ((M_DIM / BM) * (N_DIM / BN))     // 16 * 64 = 1024

// ---------------- amax/quantize grids (exact cover) ----------------
#define AMAX_X_BLOCKS 256
#define AMAX_W_BLOCKS 2048
#define QUANT_X_BLOCKS 512
#define QUANT_W_BLOCKS 4096

// ---------------- scratch (static device globals; no allocs allowed) ----------------
// codes: e4m3 encodings of 2*e2m1 codebook value, i.e. {0,1,2,3,4,6,8,12} signed
__device__ __align__(256) uint8_t g_xq[M_DIM * K_DIM];   // 2 MB
__device__ __align__(256) uint8_t g_wq[N_DIM * K_DIM];   // 16 MB
__device__ unsigned int g_amax_bits[2];                  // zero-init; last gemm CTA re-zeroes
__device__ unsigned int g_done;                          // completion counter (returns to 0)

// ---------------- PTX helpers ----------------
DINLINE uint32_t smem_u32(const void* p) {
    uint32_t a;
    asm("{ .reg .u64 t; cvta.to.shared.u64 t, %1; cvt.u32.u64 %0, t; }" : "=r"(a) : "l"(p));
    return a;
}

DINLINE void cp16(uint32_t dst, const void* src) {
    asm volatile("cp.async.cg.shared.global [%0], [%1], 16;" :: "r"(dst), "l"(src));
}
DINLINE void cp_commit() { asm volatile("cp.async.commit_group;" ::: "memory"); }

DINLINE void ldsm4(uint32_t* r, uint32_t addr) {
    asm volatile("ldmatrix.sync.aligned.m8n8.x4.shared.b16 {%0,%1,%2,%3}, [%4];"
                 : "=r"(r[0]), "=r"(r[1]), "=r"(r[2]), "=r"(r[3]) : "r"(addr));
}

// fp8 e4m3 MMA, f32 accumulate.
DINLINE void mma_f8(float* c, const uint32_t* a, const uint32_t* b) {
    asm volatile(
        "mma.sync.aligned.m16n8k32.row.col.f32.e4m3.e4m3.f32 "
        "{%0,%1,%2,%3}, {%4,%5,%6,%7}, {%8,%9}, {%0,%1,%2,%3};"
        : "+f"(c[0]), "+f"(c[1]), "+f"(c[2]), "+f"(c[3])
        : "r"(a[0]), "r"(a[1]), "r"(a[2]), "r"(a[3]), "r"(b[0]), "r"(b[1]));
}

// ---------------- phase 1: fused amax (exact fp32 max of |t|), MLP=8 ----------------
__global__ void __launch_bounds__(256) amax_kernel(const float4* __restrict__ x,
                                                   const float4* __restrict__ w) {
    const float4* in;
    int which;
    if (blockIdx.x < AMAX_X_BLOCKS) {
        in = x + (size_t)blockIdx.x * 2048;
        which = 0;
    } else {
        in = w + (size_t)(blockIdx.x - AMAX_X_BLOCKS) * 2048;
        which = 1;
    }
    float4 v[8];
#pragma unroll
    for (int j = 0; j < 8; j++) v[j] = in[threadIdx.x + j * 256];
    float m = 0.0f;
#pragma unroll
    for (int j = 0; j < 8; j++)
        m = fmaxf(m, fmaxf(fmaxf(fabsf(v[j].x), fabsf(v[j].y)),
                           fmaxf(fabsf(v[j].z), fabsf(v[j].w))));
#pragma unroll
    for (int o = 16; o; o >>= 1) m = fmaxf(m, __shfl_xor_sync(0xffffffffu, m, o));
    __shared__ float sm[8];
    if ((threadIdx.x & 31) == 0) sm[threadIdx.x >> 5] = m;
    __syncthreads();
    if (threadIdx.x == 0) {
        float b = sm[0];
#pragma unroll
        for (int i = 1; i < 8; i++) b = fmaxf(b, sm[i]);
        // values >= 0 -> int bit compare == float compare
        atomicMax(reinterpret_cast<int*>(&g_amax_bits[which]), __float_as_int(b));
    }
}

// ---------------- phase 2: fused quantize to e4m3 codes ----------------
// nearest codebook magnitude, ties -> lower. Midpoints on |t|*scale:
//   0.25, 0.75, 1.25, 1.75, 2.5, 3.5, 5.0 ; strictly-greater moves up.
// e4m3 encodings of {0,1,2,3,4,6,8,12}: 00,38,40,44,48,4C,50,54
DINLINE uint32_t qbyte(float v, float s) {
    float a = __fmul_rn(fabsf(v), s);
    int idx = a > 5.0f  ? 7
            : a > 3.5f  ? 6
            : a > 2.5f  ? 5
            : a > 1.75f ? 4
            : a > 1.25f ? 3
            : a > 0.75f ? 2
            : a > 0.25f ? 1 : 0;
    uint32_t b = (uint32_t)((0x54504C4844403800ull >> (idx * 8)) & 0xff);
    return b | (v < 0.0f ? 0x80u : 0u);
}

__global__ void __launch_bounds__(256) quantize_kernel(const float4* __restrict__ x,
                                                       const float4* __restrict__ w) {
    const float4* in;
    uint8_t* outp;
    size_t i;
    int which;
    if (blockIdx.x < QUANT_X_BLOCKS) {
        in = x; outp = g_xq; which = 0;
        i = (size_t)blockIdx.x * 256 + threadIdx.x;
    } else {
        in = w; outp = g_wq; which = 1;
        i = (size_t)(blockIdx.x - QUANT_X_BLOCKS) * 256 + threadIdx.x;
    }
    float amax = fmaxf(__uint_as_float(g_amax_bits[which]), 1e-12f);
    float s = __fdiv_rn(6.0f, amax);

    float4 v[4];
#pragma unroll
    for (int j = 0; j < 4; j++) v[j] = in[i * 4 + j];
    uint32_t wrd[4];
#pragma unroll
    for (int j = 0; j < 4; j++) {
        wrd[j] = qbyte(v[j].x, s)
               | (qbyte(v[j].y, s) << 8)
               | (qbyte(v[j].z, s) << 16)
               | (qbyte(v[j].w, s) << 24);
    }
    reinterpret_cast<uint4*>(outp)[i] = make_uint4(wrd[0], wrd[1], wrd[2], wrd[3]);
}

// ---------------- phase 3: fp8 QMMA GEMM ----------------
// C[32,64] per CTA; 4 warps (2x2), warp tile 16x32. BK=64 -> 2 k32 steps/stage.
// 1024 CTAs, 7 CTAs/SM co-resident -> near-perfect SM load balance
// (max 14336 mma/SM vs 16384 with the old 256-CTA grid).

__global__ void __launch_bounds__(128, 7) gemm_kernel(float* __restrict__ out) {
    extern __shared__ char smem[];
    uint32_t sb = smem_u32(smem);
    const int tid = threadIdx.x;
    const int lane = tid & 31, wid = tid >> 5;
    const int wm = wid & 1, wn = wid >> 1;            // 2x2 warp grid
    const int bm = blockIdx.x & 15, bn = blockIdx.x >> 4;  // bm-major: B-tile sharers adjacent
    const uint8_t* Ag = g_xq + (size_t)bm * BM * K_DIM;
    const uint8_t* Bg = g_wq + (size_t)bn * BN * K_DIM;

    // read scales NOW (zeroed only after ALL CTAs complete, via g_done)
    float ax = fmaxf(__uint_as_float(g_amax_bits[0]), 1e-12f);
    float aw = fmaxf(__uint_as_float(g_amax_bits[1]), 1e-12f);
    // scale = inv_scale_x * inv_scale_w / 4 (codes are 2x codebook values)
    float scl = __fdiv_rn(1.0f, __fdiv_rn(6.0f, ax)) *
                __fdiv_rn(1.0f, __fdiv_rn(6.0f, aw)) * 0.25f;

    // cp.async mapping: 384 x 16B chunks per stage (A 128 + B 256), 3 per thread
    uint32_t soff[3];
    const uint8_t* gp[3];
#pragma unroll
    for (int j = 0; j < 3; j++) {
        int idx = tid + j * 128;
        if (idx < 128) {                      // A: 32 rows x 4 chunks
            int row = idx >> 2, ch = idx & 3;
            soff[j] = (uint32_t)(row * ROWB + ch * 16);
            gp[j] = Ag + (size_t)row * K_DIM + ch * 16;
        } else {                              // B: 64 rows x 4 chunks
            int r2 = idx - 128;
            int row = r2 >> 2, ch = r2 & 3;
            soff[j] = (uint32_t)(TILE_A_BYTES + row * ROWB + ch * 16);
            gp[j] = Bg + (size_t)row * K_DIM + ch * 16;
        }
    }

    // per-lane ldmatrix offsets
    uint32_t offA[2], offB[2][2];
    {
        int rA = wm * 16 + (lane & 15);
        int kA = (lane & 16);
#pragma unroll
        for (int ks = 0; ks < 2; ks++)
            offA[ks] = (uint32_t)(rA * ROWB + ks * 32 + kA);
        int mB = lane >> 3;
        int rB = wn * 32 + (mB >> 1) * 8 + (lane & 7);
        int kB = (mB & 1) * 16;
#pragma unroll
        for (int np = 0; np < 2; np++)
#pragma unroll
            for (int ks = 0; ks < 2; ks++)
                offB[np][ks] = (uint32_t)(TILE_A_BYTES + (rB + np * 16) * ROWB + ks * 32 + kB);
    }

    float acc[4][4];
#pragma unroll
    for (int nt = 0; nt < 4; nt++)
#pragma unroll
        for (int i = 0; i < 4; i++) acc[nt][i] = 0.0f;

    // prologue: fill STAGES-1 stages
#pragma unroll
    for (int s = 0; s < STAGES - 1; s++) {
#pragma unroll
        for (int j = 0; j < 3; j++) cp16(sb + s * STAGE_BYTES + soff[j], gp[j] + s * BK);
        cp_commit();
    }

    for (int k = 0; k < KIT; k++) {
        const int s = k & (STAGES - 1);
        if (k < KIT - 2)       asm volatile("cp.async.wait_group 2;" ::: "memory");
        else if (k == KIT - 2) asm volatile("cp.async.wait_group 1;" ::: "memory");
        else                   asm volatile("cp.async.wait_group 0;" ::: "memory");
        __syncthreads();

        // prefetch stage k+3 into the slot retired at iteration k-1
        int kp = k + STAGES - 1;
        if (kp < KIT) {
            uint32_t sp = sb + (uint32_t)(kp & (STAGES - 1)) * STAGE_BYTES;
#pragma unroll
            for (int j = 0; j < 3; j++) cp16(sp + soff[j], gp[j] + kp * BK);
            cp_commit();
        }

        uint32_t base = sb + (uint32_t)s * STAGE_BYTES;
#pragma unroll
        for (int ks = 0; ks < 2; ks++) {
            uint32_t a[4], b[2][4];
            ldsm4(a, base + offA[ks]);
#pragma unroll
            for (int np = 0; np < 2; np++) ldsm4(b[np], base + offB[np][ks]);
#pragma unroll
            for (int nt = 0; nt < 4; nt++) {
                const uint32_t* bf = &b[nt >> 1][(nt & 1) * 2];
                mma_f8(acc[nt], a, bf);
            }
        }
    }

    // epilogue
    int row0 = bm * BM + wm * 16 + (lane >> 2);
    int col0 = bn * BN + wn * 32 + (lane & 3) * 2;
#pragma unroll
    for (int nt = 0; nt < 4; nt++) {
        float2 v0, v1;
        v0.x = acc[nt][0] * scl;
        v0.y = acc[nt][1] * scl;
        v1.x = acc[nt][2] * scl;
        v1.y = acc[nt][3] * scl;
        int c = col0 + nt * 8;
        *reinterpret_cast<float2*>(out + (size_t)row0 * N_DIM + c) = v0;
        *reinterpret_cast<float2*>(out + (size_t)(row0 + 8) * N_DIM + c) = v1;
    }

    // last CTA to finish resets amax accumulators + counter for the next replay.
    // Every CTA reads g_amax_bits in its prologue, before incrementing here.
    __syncthreads();
    if (tid == 0) {
        __threadfence();
        unsigned old = atomicAdd(&g_done, 1u);
        if (old == GRID_GEMM - 1) {
            g_amax_bits[0] = 0u;
            g_amax_bits[1] = 0u;
            g_done = 0u;
        }
    }
}

// ---------------- launch ----------------
extern "C" void kernel_launch(void* const* d_in, const int* in_sizes, int n_in,
                              void* d_out, int out_size) {
    const float* x = (const float*)d_in[0];       // [512, 4096]
    const float* w = (const float*)d_in[1];       // [4096, 4096]
    float* out = (float*)d_out;                   // [512, 4096] fp32

    cudaFuncSetAttribute(gemm_kernel, cudaFuncAttributeMaxDynamicSharedMemorySize, SMEM_TOTAL);

    amax_kernel<<<AMAX_X_BLOCKS + AMAX_W_BLOCKS, 256>>>((const float4*)x, (const float4*)w);
    quantize_kernel<<<QUANT_X_BLOCKS + QUANT_W_BLOCKS, 256>>>((const float4*)x, (const float4*)w);
    gemm_kernel<<<GRID_GEMM, 128, SMEM_TOTAL>>>(out);
}

// round 10
// speedup vs baseline: 1.1102x; 1.0145x over previous
#include <cuda_runtime.h>
#include <cstdint>

#define DINLINE __device__ __forceinline__

// ---------------- problem sizes ----------------
#define M_DIM 512
#define N_DIM 4096
#define K_DIM 4096

// ---------------- GEMM tiling: 32x64 tiles, 1024 CTAs for SM load balance ----------------
#define BM 32
#define BN 64
#define BK 64                        // fp8 elements per K-chunk
#define ROWB 80                      // padded smem row stride -> conflict-free ldmatrix
#define STAGES 4
#define KIT (K_DIM / BK)             // 64
#define TILE_A_BYTES (BM * ROWB)     // 2560
#define TILE_B_BYTES (BN * ROWB)     // 5120
#define STAGE_BYTES (TILE_A_BYTES + TILE_B_BYTES)   // 7680
#define SMEM_TOTAL (STAGES * STAGE_BYTES)           // 30720 -> 7 CTAs/SM
#define GRID_GEMM ((M_DIM / BM) * (N_DIM / BN))     // 16 * 64 = 1024

// ---------------- amax/quantize grids (exact cover) ----------------
#define AMAX_X_BLOCKS 256
#define AMAX_W_BLOCKS 2048
#define QUANT_X_BLOCKS 512
#define QUANT_W_BLOCKS 4096

// ---------------- scratch (static device globals; no allocs allowed) ----------------
// codes: e4m3 encodings of 2*e2m1 codebook value, i.e. {0,1,2,3,4,6,8,12} signed
__device__ __align__(256) uint8_t g_xq[M_DIM * K_DIM];   // 2 MB
__device__ __align__(256) uint8_t g_wq[N_DIM * K_DIM];   // 16 MB
__device__ unsigned int g_amax_bits[2];                  // zero-init; last gemm CTA re-zeroes
__device__ unsigned int g_done;                          // completion counter (returns to 0)

// ---------------- PTX helpers ----------------
DINLINE uint32_t smem_u32(const void* p) {
    uint32_t a;
    asm("{ .reg .u64 t; cvta.to.shared.u64 t, %1; cvt.u32.u64 %0, t; }" : "=r"(a) : "l"(p));
    return a;
}

DINLINE void cp16(uint32_t dst, const void* src) {
    asm volatile("cp.async.cg.shared.global [%0], [%1], 16;" :: "r"(dst), "l"(src));
}
DINLINE void cp_commit() { asm volatile("cp.async.commit_group;" ::: "memory"); }

DINLINE void ldsm4(uint32_t* r, uint32_t addr) {
    asm volatile("ldmatrix.sync.aligned.m8n8.x4.shared.b16 {%0,%1,%2,%3}, [%4];"
                 : "=r"(r[0]), "=r"(r[1]), "=r"(r[2]), "=r"(r[3]) : "r"(addr));
}

// batched (compiler-unreorderable) global v4 load — forces real MLP
DINLINE void ldg4(float4& v, const float4* p) {
    asm volatile("ld.global.nc.v4.f32 {%0,%1,%2,%3}, [%4];"
                 : "=f"(v.x), "=f"(v.y), "=f"(v.z), "=f"(v.w) : "l"(p));
}

// fp8 e4m3 MMA, f32 accumulate.
DINLINE void mma_f8(float* c, const uint32_t* a, const uint32_t* b) {
    asm volatile(
        "mma.sync.aligned.m16n8k32.row.col.f32.e4m3.e4m3.f32 "
        "{%0,%1,%2,%3}, {%4,%5,%6,%7}, {%8,%9}, {%0,%1,%2,%3};"
        : "+f"(c[0]), "+f"(c[1]), "+f"(c[2]), "+f"(c[3])
        : "r"(a[0]), "r"(a[1]), "r"(a[2]), "r"(a[3]), "r"(b[0]), "r"(b[1]));
}

// ---------------- phase 1: fused amax (exact fp32 max of |t|), forced MLP=8 ----------------
__global__ void __launch_bounds__(256) amax_kernel(const float4* __restrict__ x,
                                                   const float4* __restrict__ w) {
    const float4* in;
    int which;
    if (blockIdx.x < AMAX_X_BLOCKS) {
        in = x + (size_t)blockIdx.x * 2048;
        which = 0;
    } else {
        in = w + (size_t)(blockIdx.x - AMAX_X_BLOCKS) * 2048;
        which = 1;
    }
    float4 v[8];
    // 8 back-to-back volatile loads: ptxas cannot serialize them into ld/max pairs
    ldg4(v[0], in + threadIdx.x);
    ldg4(v[1], in + threadIdx.x + 256);
    ldg4(v[2], in + threadIdx.x + 512);
    ldg4(v[3], in + threadIdx.x + 768);
    ldg4(v[4], in + threadIdx.x + 1024);
    ldg4(v[5], in + threadIdx.x + 1280);
    ldg4(v[6], in + threadIdx.x + 1536);
    ldg4(v[7], in + threadIdx.x + 1792);
    float m = 0.0f;
#pragma unroll
    for (int j = 0; j < 8; j++)
        m = fmaxf(m, fmaxf(fmaxf(fabsf(v[j].x), fabsf(v[j].y)),
                           fmaxf(fabsf(v[j].z), fabsf(v[j].w))));
#pragma unroll
    for (int o = 16; o; o >>= 1) m = fmaxf(m, __shfl_xor_sync(0xffffffffu, m, o));
    __shared__ float sm[8];
    if ((threadIdx.x & 31) == 0) sm[threadIdx.x >> 5] = m;
    __syncthreads();
    if (threadIdx.x == 0) {
        float b = sm[0];
#pragma unroll
        for (int i = 1; i < 8; i++) b = fmaxf(b, sm[i]);
        // values >= 0 -> int bit compare == float compare
        atomicMax(reinterpret_cast<int*>(&g_amax_bits[which]), __float_as_int(b));
    }
}

// ---------------- phase 2: fused quantize to e4m3 codes, forced MLP=4 ----------------
// nearest codebook magnitude, ties -> lower. Midpoints on |t|*scale:
//   0.25, 0.75, 1.25, 1.75, 2.5, 3.5, 5.0 ; strictly-greater moves up.
// e4m3 encodings of {0,1,2,3,4,6,8,12}: 00,38,40,44,48,4C,50,54
DINLINE uint32_t qbyte(float v, float s) {
    float a = __fmul_rn(fabsf(v), s);
    int idx = a > 5.0f  ? 7
            : a > 3.5f  ? 6
            : a > 2.5f  ? 5
            : a > 1.75f ? 4
            : a > 1.25f ? 3
            : a > 0.75f ? 2
            : a > 0.25f ? 1 : 0;
    uint32_t b = (uint32_t)((0x54504C4844403800ull >> (idx * 8)) & 0xff);
    return b | (v < 0.0f ? 0x80u : 0u);
}

__global__ void __launch_bounds__(256) quantize_kernel(const float4* __restrict__ x,
                                                       const float4* __restrict__ w) {
    const float4* in;
    uint8_t* outp;
    size_t i;
    int which;
    if (blockIdx.x < QUANT_X_BLOCKS) {
        in = x; outp = g_xq; which = 0;
        i = (size_t)blockIdx.x * 256 + threadIdx.x;
    } else {
        in = w; outp = g_wq; which = 1;
        i = (size_t)(blockIdx.x - QUANT_X_BLOCKS) * 256 + threadIdx.x;
    }
    float amax = fmaxf(__uint_as_float(g_amax_bits[which]), 1e-12f);
    float s = __fdiv_rn(6.0f, amax);

    float4 v[4];
    ldg4(v[0], in + i * 4);
    ldg4(v[1], in + i * 4 + 1);
    ldg4(v[2], in + i * 4 + 2);
    ldg4(v[3], in + i * 4 + 3);
    uint32_t wrd[4];
#pragma unroll
    for (int j = 0; j < 4; j++) {
        wrd[j] = qbyte(v[j].x, s)
               | (qbyte(v[j].y, s) << 8)
               | (qbyte(v[j].z, s) << 16)
               | (qbyte(v[j].w, s) << 24);
    }
    reinterpret_cast<uint4*>(outp)[i] = make_uint4(wrd[0], wrd[1], wrd[2], wrd[3]);
}

// ---------------- phase 3: fp8 QMMA GEMM ----------------
// C[32,64] per CTA; 4 warps (2x2), warp tile 16x32. BK=64 -> 2 k32 steps/stage.
// 1024 CTAs, 7 CTAs/SM co-resident -> near-perfect SM load balance.

__global__ void __launch_bounds__(128, 7) gemm_kernel(float* __restrict__ out) {
    extern __shared__ char smem[];
    uint32_t sb = smem_u32(smem);
    const int tid = threadIdx.x;
    const int lane = tid & 31, wid = tid >> 5;
    const int wm = wid & 1, wn = wid >> 1;            // 2x2 warp grid
    const int bm = blockIdx.x & 15, bn = blockIdx.x >> 4;  // bm-major: B-tile sharers adjacent
    const uint8_t* Ag = g_xq + (size_t)bm * BM * K_DIM;
    const uint8_t* Bg = g_wq + (size_t)bn * BN * K_DIM;

    // read scales NOW (zeroed only after ALL CTAs complete, via g_done)
    float ax = fmaxf(__uint_as_float(g_amax_bits[0]), 1e-12f);
    float aw = fmaxf(__uint_as_float(g_amax_bits[1]), 1e-12f);
    // scale = inv_scale_x * inv_scale_w / 4 (codes are 2x codebook values)
    float scl = __fdiv_rn(1.0f, __fdiv_rn(6.0f, ax)) *
                __fdiv_rn(1.0f, __fdiv_rn(6.0f, aw)) * 0.25f;

    // cp.async mapping: 384 x 16B chunks per stage (A 128 + B 256), 3 per thread
    uint32_t soff[3];
    const uint8_t* gp[3];
#pragma unroll
    for (int j = 0; j < 3; j++) {
        int idx = tid + j * 128;
        if (idx < 128) {                      // A: 32 rows x 4 chunks
            int row = idx >> 2, ch = idx & 3;
            soff[j] = (uint32_t)(row * ROWB + ch * 16);
            gp[j] = Ag + (size_t)row * K_DIM + ch * 16;
        } else {                              // B: 64 rows x 4 chunks
            int r2 = idx - 128;
            int row = r2 >> 2, ch = r2 & 3;
            soff[j] = (uint32_t)(TILE_A_BYTES + row * ROWB + ch * 16);
            gp[j] = Bg + (size_t)row * K_DIM + ch * 16;
        }
    }

    // per-lane ldmatrix offsets
    uint32_t offA[2], offB[2][2];
    {
        int rA = wm * 16 + (lane & 15);
        int kA = (lane & 16);
#pragma unroll
        for (int ks = 0; ks < 2; ks++)
            offA[ks] = (uint32_t)(rA * ROWB + ks * 32 + kA);
        int mB = lane >> 3;
        int rB = wn * 32 + (mB >> 1) * 8 + (lane & 7);
        int kB = (mB & 1) * 16;
#pragma unroll
        for (int np = 0; np < 2; np++)
#pragma unroll
            for (int ks = 0; ks < 2; ks++)
                offB[np][ks] = (uint32_t)(TILE_A_BYTES + (rB + np * 16) * ROWB + ks * 32 + kB);
    }

    float acc[4][4];
#pragma unroll
    for (int nt = 0; nt < 4; nt++)
#pragma unroll
        for (int i = 0; i < 4; i++) acc[nt][i] = 0.0f;

    // prologue: fill STAGES-1 stages
#pragma unroll
    for (int s = 0; s < STAGES - 1; s++) {
#pragma unroll
        for (int j = 0; j < 3; j++) cp16(sb + s * STAGE_BYTES + soff[j], gp[j] + s * BK);
        cp_commit();
    }

    for (int k = 0; k < KIT; k++) {
        const int s = k & (STAGES - 1);
        if (k < KIT - 2)       asm volatile("cp.async.wait_group 2;" ::: "memory");
        else if (k == KIT - 2) asm volatile("cp.async.wait_group 1;" ::: "memory");
        else                   asm volatile("cp.async.wait_group 0;" ::: "memory");
        __syncthreads();

        // prefetch stage k+3 into the slot retired at iteration k-1
        int kp = k + STAGES - 1;
        if (kp < KIT) {
            uint32_t sp = sb + (uint32_t)(kp & (STAGES - 1)) * STAGE_BYTES;
#pragma unroll
            for (int j = 0; j < 3; j++) cp16(sp + soff[j], gp[j] + kp * BK);
            cp_commit();
        }

        uint32_t base = sb + (uint32_t)s * STAGE_BYTES;
#pragma unroll
        for (int ks = 0; ks < 2; ks++) {
            uint32_t a[4], b[2][4];
            ldsm4(a, base + offA[ks]);
#pragma unroll
            for (int np = 0; np < 2; np++) ldsm4(b[np], base + offB[np][ks]);
#pragma unroll
            for (int nt = 0; nt < 4; nt++) {
                const uint32_t* bf = &b[nt >> 1][(nt & 1) * 2];
                mma_f8(acc[nt], a, bf);
            }
        }
    }

    // epilogue
    int row0 = bm * BM + wm * 16 + (lane >> 2);
    int col0 = bn * BN + wn * 32 + (lane & 3) * 2;
#pragma unroll
    for (int nt = 0; nt < 4; nt++) {
        float2 v0, v1;
        v0.x = acc[nt][0] * scl;
        v0.y = acc[nt][1] * scl;
        v1.x = acc[nt][2] * scl;
        v1.y = acc[nt][3] * scl;
        int c = col0 + nt * 8;
        *reinterpret_cast<float2*>(out + (size_t)row0 * N_DIM + c) = v0;
        *reinterpret_cast<float2*>(out + (size_t)(row0 + 8) * N_DIM + c) = v1;
    }

    // last CTA to finish resets amax accumulators + counter for the next replay.
    // Every CTA reads g_amax_bits in its prologue, before incrementing here.
    __syncthreads();
    if (tid == 0) {
        __threadfence();
        unsigned old = atomicAdd(&g_done, 1u);
        if (old == GRID_GEMM - 1) {
            g_amax_bits[0] = 0u;
            g_amax_bits[1] = 0u;
            g_done = 0u;
        }
    }
}

// ---------------- launch ----------------
extern "C" void kernel_launch(void* const* d_in, const int* in_sizes, int n_in,
                              void* d_out, int out_size) {
    const float* x = (const float*)d_in[0];       // [512, 4096]
    const float* w = (const float*)d_in[1];       // [4096, 4096]
    float* out = (float*)d_out;                   // [512, 4096] fp32

    cudaFuncSetAttribute(gemm_kernel, cudaFuncAttributeMaxDynamicSharedMemorySize, SMEM_TOTAL);

    amax_kernel<<<AMAX_X_BLOCKS + AMAX_W_BLOCKS, 256>>>((const float4*)x, (const float4*)w);
    quantize_kernel<<<QUANT_X_BLOCKS + QUANT_W_BLOCKS, 256>>>((const float4*)x, (const float4*)w);
    gemm_kernel<<<GRID_GEMM, 128, SMEM_TOTAL>>>(out);
}

// round 11
// speedup vs baseline: 1.1191x; 1.0080x over previous
#include <cuda_runtime.h>
#include <cstdint>

#define DINLINE __device__ __forceinline__

// ---------------- problem sizes ----------------
#define M_DIM 512
#define N_DIM 4096
#define K_DIM 4096

// ---------------- GEMM tiling: 32x64 tiles, 1024 CTAs for SM load balance ----------------
#define BM 32
#define BN 64
#define BK 64                        // fp8 elements per K-chunk
#define ROWB 80                      // padded smem row stride -> conflict-free ldmatrix
#define STAGES 4
#define KIT (K_DIM / BK)             // 64
#define TILE_A_BYTES (BM * ROWB)     // 2560
#define TILE_B_BYTES (BN * ROWB)     // 5120
#define STAGE_BYTES (TILE_A_BYTES + TILE_B_BYTES)   // 7680
#define SMEM_TOTAL (STAGES * STAGE_BYTES)           // 30720 -> 7 CTAs/SM
#define GRID_GEMM ((M_DIM / BM) * (N_DIM / BN))     // 16 * 64 = 1024

// ---------------- amax/quantize: single-wave exact-cover grids ----------------
#define AMAX_BLOCKS 1152             // <= 1184 resident (148 SMs * 8 CTAs) -> 1 wave
#define AMAX_XB 128                  // 128 blk * 256 thr * 16 f4 = 524288 f4 = x exactly
                                     // 1024 blk * 256 * 16 = 4194304 f4 = w exactly
#define QUANT_BLOCKS 1152
#define QUANT_XB 128                 // 128 blk * 256 thr * 4 uint4 = 131072 = x outputs
                                     // 1024 blk * 256 * 4 = w outputs exactly

// ---------------- scratch (static device globals; no allocs allowed) ----------------
// codes: e4m3 encodings of 2*e2m1 codebook value, i.e. {0,1,2,3,4,6,8,12} signed
__device__ __align__(256) uint8_t g_xq[M_DIM * K_DIM];   // 2 MB
__device__ __align__(256) uint8_t g_wq[N_DIM * K_DIM];   // 16 MB
__device__ unsigned int g_amax_bits[2];                  // zero-init; last gemm CTA re-zeroes
__device__ unsigned int g_done;                          // completion counter (returns to 0)

// ---------------- PTX helpers ----------------
DINLINE uint32_t smem_u32(const void* p) {
    uint32_t a;
    asm("{ .reg .u64 t; cvta.to.shared.u64 t, %1; cvt.u32.u64 %0, t; }" : "=r"(a) : "l"(p));
    return a;
}

DINLINE void cp16(uint32_t dst, const void* src) {
    asm volatile("cp.async.cg.shared.global [%0], [%1], 16;" :: "r"(dst), "l"(src));
}
DINLINE void cp_commit() { asm volatile("cp.async.commit_group;" ::: "memory"); }

DINLINE void ldsm4(uint32_t* r, uint32_t addr) {
    asm volatile("ldmatrix.sync.aligned.m8n8.x4.shared.b16 {%0,%1,%2,%3}, [%4];"
                 : "=r"(r[0]), "=r"(r[1]), "=r"(r[2]), "=r"(r[3]) : "r"(addr));
}

// batched (compiler-unreorderable) global v4 load
DINLINE void ldg4(float4& v, const float4* p) {
    asm volatile("ld.global.nc.v4.f32 {%0,%1,%2,%3}, [%4];"
                 : "=f"(v.x), "=f"(v.y), "=f"(v.z), "=f"(v.w) : "l"(p));
}

// fp8 e4m3 MMA, f32 accumulate.
DINLINE void mma_f8(float* c, const uint32_t* a, const uint32_t* b) {
    asm volatile(
        "mma.sync.aligned.m16n8k32.row.col.f32.e4m3.e4m3.f32 "
        "{%0,%1,%2,%3}, {%4,%5,%6,%7}, {%8,%9}, {%0,%1,%2,%3};"
        : "+f"(c[0]), "+f"(c[1]), "+f"(c[2]), "+f"(c[3])
        : "r"(a[0]), "r"(a[1]), "r"(a[2]), "r"(a[3]), "r"(b[0]), "r"(b[1]));
}

DINLINE float amax8(const float4* v) {
    float m = 0.0f;
#pragma unroll
    for (int j = 0; j < 8; j++)
        m = fmaxf(m, fmaxf(fmaxf(fabsf(v[j].x), fabsf(v[j].y)),
                           fmaxf(fabsf(v[j].z), fabsf(v[j].w))));
    return m;
}

// ---------------- phase 1: amax, single wave, 16 f4/thread ----------------
__global__ void __launch_bounds__(256) amax_kernel(const float4* __restrict__ x,
                                                   const float4* __restrict__ w) {
    const float4* in;
    int which;
    if (blockIdx.x < AMAX_XB) {
        in = x + (size_t)blockIdx.x * 4096;
        which = 0;
    } else {
        in = w + (size_t)(blockIdx.x - AMAX_XB) * 4096;
        which = 1;
    }
    const float4* p = in + threadIdx.x;
    float4 v[8];
    ldg4(v[0], p);        ldg4(v[1], p + 256);  ldg4(v[2], p + 512);  ldg4(v[3], p + 768);
    ldg4(v[4], p + 1024); ldg4(v[5], p + 1280); ldg4(v[6], p + 1536); ldg4(v[7], p + 1792);
    float m = amax8(v);
    p += 2048;
    ldg4(v[0], p);        ldg4(v[1], p + 256);  ldg4(v[2], p + 512);  ldg4(v[3], p + 768);
    ldg4(v[4], p + 1024); ldg4(v[5], p + 1280); ldg4(v[6], p + 1536); ldg4(v[7], p + 1792);
    m = fmaxf(m, amax8(v));

#pragma unroll
    for (int o = 16; o; o >>= 1) m = fmaxf(m, __shfl_xor_sync(0xffffffffu, m, o));
    __shared__ float sm[8];
    if ((threadIdx.x & 31) == 0) sm[threadIdx.x >> 5] = m;
    __syncthreads();
    if (threadIdx.x == 0) {
        float b = sm[0];
#pragma unroll
        for (int i = 1; i < 8; i++) b = fmaxf(b, sm[i]);
        // values >= 0 -> int bit compare == float compare
        atomicMax(reinterpret_cast<int*>(&g_amax_bits[which]), __float_as_int(b));
    }
}

// ---------------- phase 2: quantize to e4m3 codes, single wave ----------------
// nearest codebook magnitude, ties -> lower. Midpoints on |t|*scale:
//   0.25, 0.75, 1.25, 1.75, 2.5, 3.5, 5.0 ; strictly-greater moves up.
// e4m3 encodings of {0,1,2,3,4,6,8,12}: 00,38,40,44,48,4C,50,54
DINLINE uint32_t qbyte(float v, float s) {
    float a = __fmul_rn(fabsf(v), s);
    int idx = a > 5.0f  ? 7
            : a > 3.5f  ? 6
            : a > 2.5f  ? 5
            : a > 1.75f ? 4
            : a > 1.25f ? 3
            : a > 0.75f ? 2
            : a > 0.25f ? 1 : 0;
    uint32_t b = (uint32_t)((0x54504C4844403800ull >> (idx * 8)) & 0xff);
    return b | (v < 0.0f ? 0x80u : 0u);
}

DINLINE uint32_t qword(float4 v, float s) {
    return qbyte(v.x, s) | (qbyte(v.y, s) << 8) | (qbyte(v.z, s) << 16) | (qbyte(v.w, s) << 24);
}

__global__ void __launch_bounds__(256) quantize_kernel(const float4* __restrict__ x,
                                                       const float4* __restrict__ w) {
    const float4* in;
    uint8_t* outp;
    size_t base;
    int which;
    if (blockIdx.x < QUANT_XB) {
        in = x; outp = g_xq; which = 0;
        base = (size_t)blockIdx.x * 1024 + threadIdx.x;
    } else {
        in = w; outp = g_wq; which = 1;
        base = (size_t)(blockIdx.x - QUANT_XB) * 1024 + threadIdx.x;
    }
    float amax = fmaxf(__uint_as_float(g_amax_bits[which]), 1e-12f);
    float s = __fdiv_rn(6.0f, amax);

    // 4 uint4 outputs per thread (j=0..3, stride 256): processed in pairs of 2
    // with 8 batched input loads per pair.
#pragma unroll
    for (int jp = 0; jp < 2; jp++) {
        size_t o0 = base + (size_t)(jp * 2) * 256;
        size_t o1 = o0 + 256;
        float4 v[8];
        ldg4(v[0], in + o0 * 4);     ldg4(v[1], in + o0 * 4 + 1);
        ldg4(v[2], in + o0 * 4 + 2); ldg4(v[3], in + o0 * 4 + 3);
        ldg4(v[4], in + o1 * 4);     ldg4(v[5], in + o1 * 4 + 1);
        ldg4(v[6], in + o1 * 4 + 2); ldg4(v[7], in + o1 * 4 + 3);
        reinterpret_cast<uint4*>(outp)[o0] =
            make_uint4(qword(v[0], s), qword(v[1], s), qword(v[2], s), qword(v[3], s));
        reinterpret_cast<uint4*>(outp)[o1] =
            make_uint4(qword(v[4], s), qword(v[5], s), qword(v[6], s), qword(v[7], s));
    }
}

// ---------------- phase 3: fp8 QMMA GEMM ----------------
// C[32,64] per CTA; 4 warps (2x2), warp tile 16x32. BK=64 -> 2 k32 steps/stage.
// 1024 CTAs, 7 CTAs/SM co-resident -> near-perfect SM load balance.

__global__ void __launch_bounds__(128, 7) gemm_kernel(float* __restrict__ out) {
    extern __shared__ char smem[];
    uint32_t sb = smem_u32(smem);
    const int tid = threadIdx.x;
    const int lane = tid & 31, wid = tid >> 5;
    const int wm = wid & 1, wn = wid >> 1;            // 2x2 warp grid
    const int bm = blockIdx.x & 15, bn = blockIdx.x >> 4;  // bm-major: B-tile sharers adjacent
    const uint8_t* Ag = g_xq + (size_t)bm * BM * K_DIM;
    const uint8_t* Bg = g_wq + (size_t)bn * BN * K_DIM;

    // read scales NOW (zeroed only after ALL CTAs complete, via g_done)
    float ax = fmaxf(__uint_as_float(g_amax_bits[0]), 1e-12f);
    float aw = fmaxf(__uint_as_float(g_amax_bits[1]), 1e-12f);
    // scale = inv_scale_x * inv_scale_w / 4 (codes are 2x codebook values)
    float scl = __fdiv_rn(1.0f, __fdiv_rn(6.0f, ax)) *
                __fdiv_rn(1.0f, __fdiv_rn(6.0f, aw)) * 0.25f;

    // cp.async mapping: 384 x 16B chunks per stage (A 128 + B 256), 3 per thread
    uint32_t soff[3];
    const uint8_t* gp[3];
#pragma unroll
    for (int j = 0; j < 3; j++) {
        int idx = tid + j * 128;
        if (idx < 128) {                      // A: 32 rows x 4 chunks
            int row = idx >> 2, ch = idx & 3;
            soff[j] = (uint32_t)(row * ROWB + ch * 16);
            gp[j] = Ag + (size_t)row * K_DIM + ch * 16;
        } else {                              // B: 64 rows x 4 chunks
            int r2 = idx - 128;
            int row = r2 >> 2, ch = r2 & 3;
            soff[j] = (uint32_t)(TILE_A_BYTES + row * ROWB + ch * 16);
            gp[j] = Bg + (size_t)row * K_DIM + ch * 16;
        }
    }

    // per-lane ldmatrix offsets
    uint32_t offA[2], offB[2][2];
    {
        int rA = wm * 16 + (lane & 15);
        int kA = (lane & 16);
#pragma unroll
        for (int ks = 0; ks < 2; ks++)
            offA[ks] = (uint32_t)(rA * ROWB + ks * 32 + kA);
        int mB = lane >> 3;
        int rB = wn * 32 + (mB >> 1) * 8 + (lane & 7);
        int kB = (mB & 1) * 16;
#pragma unroll
        for (int np = 0; np < 2; np++)
#pragma unroll
            for (int ks = 0; ks < 2; ks++)
                offB[np][ks] = (uint32_t)(TILE_A_BYTES + (rB + np * 16) * ROWB + ks * 32 + kB);
    }

    float acc[4][4];
#pragma unroll
    for (int nt = 0; nt < 4; nt++)
#pragma unroll
        for (int i = 0; i < 4; i++) acc[nt][i] = 0.0f;

    // prologue: fill STAGES-1 stages
#pragma unroll
    for (int s = 0; s < STAGES - 1; s++) {
#pragma unroll
        for (int j = 0; j < 3; j++) cp16(sb + s * STAGE_BYTES + soff[j], gp[j] + s * BK);
        cp_commit();
    }

    for (int k = 0; k < KIT; k++) {
        const int s = k & (STAGES - 1);
        if (k < KIT - 2)       asm volatile("cp.async.wait_group 2;" ::: "memory");
        else if (k == KIT - 2) asm volatile("cp.async.wait_group 1;" ::: "memory");
        else                   asm volatile("cp.async.wait_group 0;" ::: "memory");
        __syncthreads();

        // prefetch stage k+3 into the slot retired at iteration k-1
        int kp = k + STAGES - 1;
        if (kp < KIT) {
            uint32_t sp = sb + (uint32_t)(kp & (STAGES - 1)) * STAGE_BYTES;
#pragma unroll
            for (int j = 0; j < 3; j++) cp16(sp + soff[j], gp[j] + kp * BK);
            cp_commit();
        }

        uint32_t base = sb + (uint32_t)s * STAGE_BYTES;
#pragma unroll
        for (int ks = 0; ks < 2; ks++) {
            uint32_t a[4], b[2][4];
            ldsm4(a, base + offA[ks]);
#pragma unroll
            for (int np = 0; np < 2; np++) ldsm4(b[np], base + offB[np][ks]);
#pragma unroll
            for (int nt = 0; nt < 4; nt++) {
                const uint32_t* bf = &b[nt >> 1][(nt & 1) * 2];
                mma_f8(acc[nt], a, bf);
            }
        }
    }

    // epilogue
    int row0 = bm * BM + wm * 16 + (lane >> 2);
    int col0 = bn * BN + wn * 32 + (lane & 3) * 2;
#pragma unroll
    for (int nt = 0; nt < 4; nt++) {
        float2 v0, v1;
        v0.x = acc[nt][0] * scl;
        v0.y = acc[nt][1] * scl;
        v1.x = acc[nt][2] * scl;
        v1.y = acc[nt][3] * scl;
        int c = col0 + nt * 8;
        *reinterpret_cast<float2*>(out + (size_t)row0 * N_DIM + c) = v0;
        *reinterpret_cast<float2*>(out + (size_t)(row0 + 8) * N_DIM + c) = v1;
    }

    // last CTA to finish resets amax accumulators + counter for the next replay.
    // Every CTA reads g_amax_bits in its prologue, before incrementing here.
    __syncthreads();
    if (tid == 0) {
        __threadfence();
        unsigned old = atomicAdd(&g_done, 1u);
        if (old == GRID_GEMM - 1) {
            g_amax_bits[0] = 0u;
            g_amax_bits[1] = 0u;
            g_done = 0u;
        }
    }
}

// ---------------- launch ----------------
extern "C" void kernel_launch(void* const* d_in, const int* in_sizes, int n_in,
                              void* d_out, int out_size) {
    const float* x = (const float*)d_in[0];       // [512, 4096]
    const float* w = (const float*)d_in[1];       // [4096, 4096]
    float* out = (float*)d_out;                   // [512, 4096] fp32

    cudaFuncSetAttribute(gemm_kernel, cudaFuncAttributeMaxDynamicSharedMemorySize, SMEM_TOTAL);

    amax_kernel<<<AMAX_BLOCKS, 256>>>((const float4*)x, (const float4*)w);
    quantize_kernel<<<QUANT_BLOCKS, 256>>>((const float4*)x, (const float4*)w);
    gemm_kernel<<<GRID_GEMM, 128, SMEM_TOTAL>>>(out);
}